// round 16
// baseline (speedup 1.0000x reference)
#include <cuda_runtime.h>
#include <math.h>

// Problem constants (B,T,D,U) = (256, 1024, 128, 256)
#define RNN_B 256
#define RNN_T 1024
#define RNN_D 128
#define RNN_U 256

// Scan K-quarter split: per quarter (64 rows), 44 rows of Wh in registers,
// 20 rows streamed from L1 with a rolling 4-row register prefetch.
#define KREG 44
#define KLDG 20

typedef unsigned long long u64;

// ---------------------------------------------------------------------------
// Packed fp32x2 helpers (Blackwell FFMA2 path — only reachable via PTX)
// ---------------------------------------------------------------------------
__device__ __forceinline__ u64 ffma2(u64 a, u64 b, u64 c) {
    u64 d;
    asm("fma.rn.f32x2 %0, %1, %2, %3;" : "=l"(d) : "l"(a), "l"(b), "l"(c));
    return d;
}
__device__ __forceinline__ u64 fadd2(u64 a, u64 b) {
    u64 d;
    asm("add.rn.f32x2 %0, %1, %2;" : "=l"(d) : "l"(a), "l"(b));
    return d;
}
__device__ __forceinline__ u64 pack2(float x, float y) {
    u64 r;
    asm("mov.b64 %0, {%1, %2};" : "=l"(r) : "f"(x), "f"(y));
    return r;
}
__device__ __forceinline__ void unpack2(u64 v, float& x, float& y) {
    asm("mov.b64 {%0, %1}, %2;" : "=f"(x), "=f"(y) : "l"(v));
}

// Fast accurate-enough tanh: 1 - 2/(e^{2x}+1). Saturates correctly. ~1e-6 err.
__device__ __forceinline__ float tanh_fast(float x) {
    float e = __expf(2.0f * x);
    return 1.0f - __fdividef(2.0f, e + 1.0f);
}

// ---------------------------------------------------------------------------
// Kernel 1: x_proj = x @ Wx + bias -> d_out (scan overwrites in place).
// 256 threads/CTA, 32-row tiles, high occupancy (32 KB smem, ~60 regs).
//   g = tid>>7: row subgroup (16 rows), p = tid&127: single u-pair (2p,2p+1).
// Per d-iter per warp: 32 FFMA2 vs ~20 l1tex wavefronts (16 broadcast LDS.128
// x loads + 2 LDG.64 weight loads of 2 wf each) -> fma-bound.
// Wx (128 KB) is L1-resident across CTAs resident on the same SM.
// ---------------------------------------------------------------------------
__global__ __launch_bounds__(256) void xproj_kernel(
        const float* __restrict__ x, const float* __restrict__ W,
        const float* __restrict__ bias, float* __restrict__ out) {
    __shared__ u64 sx[32 * RNN_D];               // 32 KB, duplicated x tile

    const int tid = threadIdx.x;
    const int g = tid >> 7;                      // row subgroup 0..1 (16 rows)
    const int p = tid & 127;                     // u-pair index
    const size_t r0 = (size_t)blockIdx.x * 32;   // first (b*t) row of tile

    // Stage x tile, duplicated into both f32x2 lanes (coalesced LDG).
    for (int idx = tid; idx < 32 * RNN_D; idx += 256) {
        int r = idx >> 7;
        int d = idx & 127;
        float v = x[(r0 + r) * RNN_D + d];
        sx[idx] = pack2(v, v);
    }
    __syncthreads();

    const u64 b2 = *reinterpret_cast<const u64*>(bias + 2 * p);
    u64 acc[16];
#pragma unroll
    for (int r = 0; r < 16; r++) acc[r] = b2;

    // Wx = W[U:], row-major (D rows of U floats) = 128 u64-pairs per row.
    const u64* wp = reinterpret_cast<const u64*>(W + (size_t)RNN_U * RNN_U) + p;
    const u64* sxg = sx + (g * 16) * RNN_D;      // this subgroup's 16 rows

#pragma unroll 4
    for (int d = 0; d < RNN_D; d += 2) {
        u64 w0 = __ldg(wp + (size_t)d * 128);
        u64 w1 = __ldg(wp + (size_t)(d + 1) * 128);
#pragma unroll
        for (int r = 0; r < 16; r++) {
            ulonglong2 xv = *reinterpret_cast<const ulonglong2*>(
                sxg + r * RNN_D + d);            // {x[r][d]dup, x[r][d+1]dup}
            acc[r] = ffma2(w0, xv.x, acc[r]);
            acc[r] = ffma2(w1, xv.y, acc[r]);
        }
    }

#pragma unroll
    for (int r = 0; r < 16; r++)
        *reinterpret_cast<u64*>(out + (r0 + g * 16 + r) * RNN_U + 2 * p) =
            acc[r];
}

// ---------------------------------------------------------------------------
// Kernel 2: persistent batch-parallel scan. 128 CTAs, 2 batches each, 256 thr.
//   s = tid>>6 : K-quarter (k in [64s, 64s+64))
//   p = tid&63 : u-quad (pairs 2p, 2p+1)
// Wh rows [64s, 64s+44) in registers (88 u64/thread); rows [64s+44, 64s+64)
// streamed from L1 with a rolling 4-row register prefetch (loads issued a
// full chunk ahead; chunk 0 issued BEFORE the 44-row register MAC).
// h duplicated {h,h}: broadcast LDS.128 = 2 dup-pairs per crossbar phase.
//
// Finalize ownership aligned with reader groups: group s finalizes exactly
// h[*, 64s..64s+64) (both batches), so the post-finalize sync is a correct
// group-local 64-thread named barrier (fixes round-14's latent cross-group
// race AND keeps the cheap barrier).
// ---------------------------------------------------------------------------
__global__ __launch_bounds__(256, 1) void rnn_scan_kernel(
        const float* __restrict__ W, const float* __restrict__ h0,
        float* __restrict__ out) {
    __shared__ u64 sh[2 * RNN_U];           // [batch][u] dup h (4 KB)
    __shared__ u64 sred[2 * 2 * 4 * 128];   // [parity][batch][group][pair] (16 KB)

    const int tid = threadIdx.x;
    const int s = tid >> 6;                 // K-quarter
    const int p = tid & 63;                 // u-quad
    const int b0 = blockIdx.x * 2;

    // Register-resident Wh: k = 64s + j, j in [0,KREG); 2 u64/row.
    u64 wr0[KREG], wr1[KREG];
    {
        const float* wb = W + (size_t)(64 * s) * RNN_U + 4 * p;
#pragma unroll
        for (int j = 0; j < KREG; j++) {
            ulonglong2 w = *reinterpret_cast<const ulonglong2*>(
                wb + (size_t)j * RNN_U);
            wr0[j] = w.x;
            wr1[j] = w.y;
        }
    }
    // Streamed tail rows k = 64s + KREG + j, j in [0,KLDG), as ulonglong2.
    const float* wtail = W + (size_t)(64 * s + KREG) * RNN_U + 4 * p;

    // Initial h from h0 (duplicated lanes).
    for (int idx = tid; idx < 2 * RNN_U; idx += 256) {
        int b = idx >> 8;
        int u = idx & 255;
        float h = h0[(size_t)(b0 + b) * RNN_U + u];
        sh[idx] = pack2(h, h);
    }
    __syncthreads();

    const u64* sh0 = sh + 64 * s;           // batch 0 h slice, this quarter
    const u64* sh1 = sh + RNN_U + 64 * s;   // batch 1

    // Finalize task: group s owns h values [64s, 64s+64).
    //   fb = p>>5 (batch), fpp = 32s + (p&31) (pair) -> values 2fpp, 2fpp+1.
    const int fb  = p >> 5;
    const int fpp = 32 * s + (p & 31);
    float* fout = out + (size_t)(b0 + fb) * RNN_T * RNN_U + 2 * fpp;
    u64* fsh = sh + fb * RNN_U + 2 * fpp;

    for (int t = 0; t < RNN_T; t++) {
        const int buf = t & 1;

        // Prefetch this step's x_proj (consumed after the full barrier).
        u64 xp = *reinterpret_cast<const u64*>(fout + (size_t)t * RNN_U);

        // Prefetch tail-weight chunk 0 (covered by the register MAC below).
        ulonglong2 wt[4];
#pragma unroll
        for (int j = 0; j < 4; j++)
            wt[j] = __ldg(reinterpret_cast<const ulonglong2*>(
                wtail + (size_t)j * RNN_U));

        u64 a00 = 0, a01 = 0, a10 = 0, a11 = 0;  // [pair][batch]

        // Register-weight MACs: 44 rows, 2 batches, 2 pairs.
#pragma unroll
        for (int j = 0; j < KREG; j += 2) {
            ulonglong2 hb0 = *reinterpret_cast<const ulonglong2*>(sh0 + j);
            ulonglong2 hb1 = *reinterpret_cast<const ulonglong2*>(sh1 + j);
            a00 = ffma2(wr0[j],     hb0.x, a00);
            a01 = ffma2(wr1[j],     hb0.x, a01);
            a10 = ffma2(wr0[j],     hb1.x, a10);
            a11 = ffma2(wr1[j],     hb1.x, a11);
            a00 = ffma2(wr0[j + 1], hb0.y, a00);
            a01 = ffma2(wr1[j + 1], hb0.y, a01);
            a10 = ffma2(wr0[j + 1], hb1.y, a10);
            a11 = ffma2(wr1[j + 1], hb1.y, a11);
        }

        // Streamed-weight MACs: 5 chunks of 4 rows, rolling prefetch.
#pragma unroll
        for (int c = 0; c < KLDG; c += 4) {
            ulonglong2 wn[4];
            if (c + 4 < KLDG) {
#pragma unroll
                for (int j = 0; j < 4; j++)
                    wn[j] = __ldg(reinterpret_cast<const ulonglong2*>(
                        wtail + (size_t)(c + 4 + j) * RNN_U));
            }
#pragma unroll
            for (int j = 0; j < 4; j += 2) {
                ulonglong2 hb0 = *reinterpret_cast<const ulonglong2*>(
                    sh0 + KREG + c + j);
                ulonglong2 hb1 = *reinterpret_cast<const ulonglong2*>(
                    sh1 + KREG + c + j);
                a00 = ffma2(wt[j].x,     hb0.x, a00);
                a01 = ffma2(wt[j].y,     hb0.x, a01);
                a10 = ffma2(wt[j].x,     hb1.x, a10);
                a11 = ffma2(wt[j].y,     hb1.x, a11);
                a00 = ffma2(wt[j + 1].x, hb0.y, a00);
                a01 = ffma2(wt[j + 1].y, hb0.y, a01);
                a10 = ffma2(wt[j + 1].x, hb1.y, a10);
                a11 = ffma2(wt[j + 1].y, hb1.y, a11);
            }
#pragma unroll
            for (int j = 0; j < 4; j++) wt[j] = wn[j];
        }

        // Publish partials (parity-buffered against cross-step WAR).
        *reinterpret_cast<ulonglong2*>(
            &sred[((buf * 2 + 0) * 4 + s) * 128 + 2 * p]) =
            make_ulonglong2(a00, a01);
        *reinterpret_cast<ulonglong2*>(
            &sred[((buf * 2 + 1) * 4 + s) * 128 + 2 * p]) =
            make_ulonglong2(a10, a11);
        __syncthreads();   // all partials visible; all sh reads complete

        // Distributed finalize: group s reduces its own h-slice.
        {
            const u64* rb = &sred[(buf * 2 + fb) * 4 * 128 + fpp];
            u64 z = fadd2(fadd2(rb[0], rb[128]), fadd2(rb[256], rb[384]));
            z = fadd2(z, xp);
            float f0, f1;
            unpack2(z, f0, f1);
            f0 = tanh_fast(f0);
            f1 = tanh_fast(f1);
            // Output (overwrites x_proj slot for this t, in place).
            *reinterpret_cast<u64*>(fout + (size_t)t * RNN_U) = pack2(f0, f1);
            // Refresh duplicated h — values [64s,64s+64) only, read solely
            // by group s next step.
            *reinterpret_cast<ulonglong2*>(fsh) =
                make_ulonglong2(pack2(f0, f0), pack2(f1, f1));
        }
        // Correct group-local barrier: writers and readers of this h-slice
        // are exactly the 64 threads of group s.
        asm volatile("bar.sync %0, %1;" :: "r"(s + 1), "r"(64) : "memory");
    }
}

// ---------------------------------------------------------------------------
// Launch: x_proj fills d_out, then the scan rewrites it in place.
// Inputs (metadata order): x, h0, W, bias. Output dtype float32.
// ---------------------------------------------------------------------------
extern "C" void kernel_launch(void* const* d_in, const int* in_sizes, int n_in,
                              void* d_out, int out_size) {
    const float* x    = (const float*)d_in[0];
    const float* h0   = (const float*)d_in[1];
    const float* W    = (const float*)d_in[2];
    const float* bias = (const float*)d_in[3];
    float* out = (float*)d_out;

    xproj_kernel<<<(RNN_B * RNN_T) / 32, 256>>>(x, W, bias, out);
    rnn_scan_kernel<<<RNN_B / 2, 256>>>(W, h0, out);
}